// round 1
// baseline (speedup 1.0000x reference)
#include <cuda_runtime.h>
#include <math.h>

#define TOTAL 4608
#define DMODEL 768
#define NHEAD 12
#define DHEAD 64
#define DFF 3072

// -------- scratch (no allocs allowed; __device__ globals) --------
__device__ float g_xn  [TOTAL * DMODEL];
__device__ float g_qkv [TOTAL * 3 * DMODEL];
__device__ float g_attn[TOTAL * DMODEL];
__device__ float g_x1  [TOTAL * DMODEL];
__device__ float g_h   [TOTAL * DFF];

// static ragged layout: LENS = 1024,896,768,640,512,448,256,64
__constant__ int c_cu[9]  = {0, 1024, 1920, 2688, 3328, 3840, 4288, 4544, 4608};
__constant__ int c_pfx[9] = {0, 16, 30, 42, 52, 60, 67, 71, 72}; // prefix of ceil(L/64)

// ---------------- LayerNorm: one block per token ----------------
__global__ __launch_bounds__(256) void ln_kernel(const float* __restrict__ x,
                                                 const float* __restrict__ w,
                                                 const float* __restrict__ b,
                                                 float* __restrict__ out) {
    int row = blockIdx.x;
    const float* xr = x + (size_t)row * DMODEL;
    int t = threadIdx.x;
    float v[3];
    float s = 0.f, ss = 0.f;
#pragma unroll
    for (int i = 0; i < 3; i++) {
        v[i] = xr[t + 256 * i];
        s += v[i];
        ss += v[i] * v[i];
    }
#pragma unroll
    for (int off = 16; off; off >>= 1) {
        s  += __shfl_xor_sync(0xffffffffu, s, off);
        ss += __shfl_xor_sync(0xffffffffu, ss, off);
    }
    __shared__ float sh[16];
    if ((t & 31) == 0) { sh[t >> 5] = s; sh[(t >> 5) + 8] = ss; }
    __syncthreads();
    float ts = 0.f, tss = 0.f;
#pragma unroll
    for (int i = 0; i < 8; i++) { ts += sh[i]; tss += sh[i + 8]; }
    float mu  = ts * (1.f / DMODEL);
    float var = tss * (1.f / DMODEL) - mu * mu;
    float rstd = rsqrtf(var + 1e-6f);
    float* orow = out + (size_t)row * DMODEL;
#pragma unroll
    for (int i = 0; i < 3; i++) {
        int c = t + 256 * i;
        orow[c] = (v[i] - mu) * rstd * w[c] + b[c];
    }
}

// ---------------- SGEMM: C[M,N] = A[M,K] * B[N,K]^T + bias, fused epilogues ---
// EPI 0: bias only     EPI 1: bias + exact GELU     EPI 2: res + gamma*(acc+bias)
template <int EPI>
__global__ __launch_bounds__(256) void sgemm_tn(const float* __restrict__ A,
                                                const float* __restrict__ B,
                                                const float* __restrict__ bias,
                                                float* __restrict__ C,
                                                int K, int N,
                                                const float* __restrict__ res,
                                                const float* __restrict__ gamma) {
    __shared__ float As[16][128];
    __shared__ float Bs[16][128];
    int tid = threadIdx.x;
    int tx = tid & 15, ty = tid >> 4;
    int bm = blockIdx.x * 128, bn = blockIdx.y * 128;
    int lr = tid >> 2;
    int lk = (tid & 3) << 2;
    const float* Ap = A + (size_t)(bm + lr) * K + lk;
    const float* Bp = B + (size_t)(bn + lr) * K + lk;
    float acc[8][8] = {};
    for (int k0 = 0; k0 < K; k0 += 16) {
        float4 a0 = *(const float4*)(Ap);
        float4 a1 = *(const float4*)(Ap + (size_t)64 * K);
        float4 b0 = *(const float4*)(Bp);
        float4 b1 = *(const float4*)(Bp + (size_t)64 * K);
        Ap += 16; Bp += 16;
        __syncthreads();
        As[lk + 0][lr] = a0.x; As[lk + 1][lr] = a0.y; As[lk + 2][lr] = a0.z; As[lk + 3][lr] = a0.w;
        As[lk + 0][lr + 64] = a1.x; As[lk + 1][lr + 64] = a1.y; As[lk + 2][lr + 64] = a1.z; As[lk + 3][lr + 64] = a1.w;
        Bs[lk + 0][lr] = b0.x; Bs[lk + 1][lr] = b0.y; Bs[lk + 2][lr] = b0.z; Bs[lk + 3][lr] = b0.w;
        Bs[lk + 0][lr + 64] = b1.x; Bs[lk + 1][lr + 64] = b1.y; Bs[lk + 2][lr + 64] = b1.z; Bs[lk + 3][lr + 64] = b1.w;
        __syncthreads();
#pragma unroll
        for (int kk = 0; kk < 16; kk++) {
            float4 A0 = ((const float4*)As[kk])[ty];
            float4 A1 = ((const float4*)As[kk])[ty + 16];
            float4 B0 = ((const float4*)Bs[kk])[tx];
            float4 B1 = ((const float4*)Bs[kk])[tx + 16];
            float a[8] = {A0.x, A0.y, A0.z, A0.w, A1.x, A1.y, A1.z, A1.w};
            float b[8] = {B0.x, B0.y, B0.z, B0.w, B1.x, B1.y, B1.z, B1.w};
#pragma unroll
            for (int i = 0; i < 8; i++)
#pragma unroll
                for (int j = 0; j < 8; j++) acc[i][j] += a[i] * b[j];
        }
    }
#pragma unroll
    for (int i = 0; i < 8; i++) {
        int ri = bm + ((i < 4) ? (4 * ty + i) : (64 + 4 * ty + i - 4));
#pragma unroll
        for (int j = 0; j < 8; j++) {
            int cj = bn + ((j < 4) ? (4 * tx + j) : (64 + 4 * tx + j - 4));
            float v = acc[i][j] + bias[cj];
            if (EPI == 1) v = 0.5f * v * (1.f + erff(v * 0.70710678118654752f));
            if (EPI == 2) v = res[(size_t)ri * N + cj] + gamma[cj] * v;
            C[(size_t)ri * N + cj] = v;
        }
    }
}

// ---------------- Flash attention, ragged, one block per (seq, head, q-tile64) ---
__global__ __launch_bounds__(256) void attn_kernel(const float* __restrict__ qkv,
                                                   float* __restrict__ out) {
    __shared__ float Qt[64][64];   // Qt[d][q]
    __shared__ float Kt[64][64];   // Kt[d][k]
    __shared__ float Vs[64][64];   // Vs[k][d]
    __shared__ float Pk[64][65];   // Pk[k][q], padded

    int bx = blockIdx.x;
    int h  = blockIdx.y;
    int s = 0;
#pragma unroll
    for (int i = 1; i < 8; i++) s += (bx >= c_pfx[i]) ? 1 : 0;
    int q0   = (bx - c_pfx[s]) * 64;
    int base = c_cu[s];
    int L    = c_cu[s + 1] - base;

    int tid = threadIdx.x;
    int tq = tid >> 4, tk = tid & 15;
    int ltok = tid >> 2;
    int dg   = (tid & 3) << 4;

    // ---- load Q tile (transposed into smem) ----
    {
        int r = q0 + ltok;
        if (r < L) {
            const float* p = qkv + (size_t)(base + r) * 2304 + h * 64 + dg;
            float4 r0 = *(const float4*)(p);
            float4 r1 = *(const float4*)(p + 4);
            float4 r2 = *(const float4*)(p + 8);
            float4 r3 = *(const float4*)(p + 12);
            Qt[dg +  0][ltok] = r0.x; Qt[dg +  1][ltok] = r0.y; Qt[dg +  2][ltok] = r0.z; Qt[dg +  3][ltok] = r0.w;
            Qt[dg +  4][ltok] = r1.x; Qt[dg +  5][ltok] = r1.y; Qt[dg +  6][ltok] = r1.z; Qt[dg +  7][ltok] = r1.w;
            Qt[dg +  8][ltok] = r2.x; Qt[dg +  9][ltok] = r2.y; Qt[dg + 10][ltok] = r2.z; Qt[dg + 11][ltok] = r2.w;
            Qt[dg + 12][ltok] = r3.x; Qt[dg + 13][ltok] = r3.y; Qt[dg + 14][ltok] = r3.z; Qt[dg + 15][ltok] = r3.w;
        } else {
#pragma unroll
            for (int c = 0; c < 16; c++) Qt[dg + c][ltok] = 0.f;
        }
    }

    float m[4], l[4], acc[4][4];
#pragma unroll
    for (int i = 0; i < 4; i++) {
        m[i] = -1e30f; l[i] = 0.f;
#pragma unroll
        for (int j = 0; j < 4; j++) acc[i][j] = 0.f;
    }

    int nkt = (L + 63) >> 6;
    for (int kt = 0; kt < nkt; kt++) {
        int kb = kt << 6;
        __syncthreads();  // protect Kt/Vs/Pk from previous iteration readers
        {
            int r = kb + ltok;
            if (r < L) {
                const float* kp = qkv + (size_t)(base + r) * 2304 + 768 + h * 64 + dg;
                float4 k0 = *(const float4*)(kp);
                float4 k1 = *(const float4*)(kp + 4);
                float4 k2 = *(const float4*)(kp + 8);
                float4 k3 = *(const float4*)(kp + 12);
                Kt[dg +  0][ltok] = k0.x; Kt[dg +  1][ltok] = k0.y; Kt[dg +  2][ltok] = k0.z; Kt[dg +  3][ltok] = k0.w;
                Kt[dg +  4][ltok] = k1.x; Kt[dg +  5][ltok] = k1.y; Kt[dg +  6][ltok] = k1.z; Kt[dg +  7][ltok] = k1.w;
                Kt[dg +  8][ltok] = k2.x; Kt[dg +  9][ltok] = k2.y; Kt[dg + 10][ltok] = k2.z; Kt[dg + 11][ltok] = k2.w;
                Kt[dg + 12][ltok] = k3.x; Kt[dg + 13][ltok] = k3.y; Kt[dg + 14][ltok] = k3.z; Kt[dg + 15][ltok] = k3.w;
                const float* vp = kp + 768;
                float4 v0 = *(const float4*)(vp);
                float4 v1 = *(const float4*)(vp + 4);
                float4 v2 = *(const float4*)(vp + 8);
                float4 v3 = *(const float4*)(vp + 12);
                ((float4*)Vs[ltok])[(dg >> 2) + 0] = v0;
                ((float4*)Vs[ltok])[(dg >> 2) + 1] = v1;
                ((float4*)Vs[ltok])[(dg >> 2) + 2] = v2;
                ((float4*)Vs[ltok])[(dg >> 2) + 3] = v3;
            } else {
#pragma unroll
                for (int c = 0; c < 16; c++) { Kt[dg + c][ltok] = 0.f; Vs[ltok][dg + c] = 0.f; }
            }
        }
        __syncthreads();

        // ---- S = Q K^T (4x4 micro-tile per thread) ----
        float sreg[4][4] = {};
#pragma unroll 8
        for (int d = 0; d < 64; d++) {
            float4 qv = ((const float4*)Qt[d])[tq];
            float4 kv = ((const float4*)Kt[d])[tk];
            sreg[0][0] += qv.x * kv.x; sreg[0][1] += qv.x * kv.y; sreg[0][2] += qv.x * kv.z; sreg[0][3] += qv.x * kv.w;
            sreg[1][0] += qv.y * kv.x; sreg[1][1] += qv.y * kv.y; sreg[1][2] += qv.y * kv.z; sreg[1][3] += qv.y * kv.w;
            sreg[2][0] += qv.z * kv.x; sreg[2][1] += qv.z * kv.y; sreg[2][2] += qv.z * kv.z; sreg[2][3] += qv.z * kv.w;
            sreg[3][0] += qv.w * kv.x; sreg[3][1] += qv.w * kv.y; sreg[3][2] += qv.w * kv.z; sreg[3][3] += qv.w * kv.w;
        }

        // ---- online softmax update (row groups = 16 threads sharing tq) ----
        float alpha[4];
#pragma unroll
        for (int i = 0; i < 4; i++) {
            float rmax = -1e30f;
#pragma unroll
            for (int j = 0; j < 4; j++) {
                float sv = sreg[i][j] * 0.125f;
                if (kb + 4 * tk + j >= L) sv = -1e30f;
                sreg[i][j] = sv;
                rmax = fmaxf(rmax, sv);
            }
#pragma unroll
            for (int off = 8; off; off >>= 1)
                rmax = fmaxf(rmax, __shfl_xor_sync(0xffffffffu, rmax, off));
            float nm = fmaxf(m[i], rmax);
            alpha[i] = __expf(m[i] - nm);
            m[i] = nm;
            float rs = 0.f;
#pragma unroll
            for (int j = 0; j < 4; j++) {
                float p = __expf(sreg[i][j] - nm);
                sreg[i][j] = p;
                rs += p;
            }
#pragma unroll
            for (int off = 8; off; off >>= 1)
                rs += __shfl_xor_sync(0xffffffffu, rs, off);
            l[i] = l[i] * alpha[i] + rs;
        }
#pragma unroll
        for (int i = 0; i < 4; i++)
#pragma unroll
            for (int j = 0; j < 4; j++) {
                Pk[4 * tk + j][4 * tq + i] = sreg[i][j];
                acc[i][j] *= alpha[i];
            }
        __syncthreads();

        // ---- O += P V (thread covers rows 4tq.., d-cols 4tk..) ----
#pragma unroll 4
        for (int k = 0; k < 64; k++) {
            float4 vv = ((const float4*)Vs[k])[tk];
            float p0 = Pk[k][4 * tq + 0];
            float p1 = Pk[k][4 * tq + 1];
            float p2 = Pk[k][4 * tq + 2];
            float p3 = Pk[k][4 * tq + 3];
            acc[0][0] += p0 * vv.x; acc[0][1] += p0 * vv.y; acc[0][2] += p0 * vv.z; acc[0][3] += p0 * vv.w;
            acc[1][0] += p1 * vv.x; acc[1][1] += p1 * vv.y; acc[1][2] += p1 * vv.z; acc[1][3] += p1 * vv.w;
            acc[2][0] += p2 * vv.x; acc[2][1] += p2 * vv.y; acc[2][2] += p2 * vv.z; acc[2][3] += p2 * vv.w;
            acc[3][0] += p3 * vv.x; acc[3][1] += p3 * vv.y; acc[3][2] += p3 * vv.z; acc[3][3] += p3 * vv.w;
        }
    }

#pragma unroll
    for (int i = 0; i < 4; i++) {
        int r = q0 + 4 * tq + i;
        if (r < L) {
            float inv = 1.f / l[i];
            float4 o;
            o.x = acc[i][0] * inv; o.y = acc[i][1] * inv;
            o.z = acc[i][2] * inv; o.w = acc[i][3] * inv;
            *(float4*)(out + (size_t)(base + r) * 768 + h * 64 + 4 * tk) = o;
        }
    }
}

// ---------------- launch ----------------
extern "C" void kernel_launch(void* const* d_in, const int* in_sizes, int n_in,
                              void* d_out, int out_size) {
    const float* x      = (const float*)d_in[0];
    const float* n1w    = (const float*)d_in[1];
    const float* n1b    = (const float*)d_in[2];
    const float* qkv_w  = (const float*)d_in[3];
    const float* qkv_b  = (const float*)d_in[4];
    const float* proj_w = (const float*)d_in[5];
    const float* proj_b = (const float*)d_in[6];
    const float* ls1    = (const float*)d_in[7];
    const float* n2w    = (const float*)d_in[8];
    const float* n2b    = (const float*)d_in[9];
    const float* fc1_w  = (const float*)d_in[10];
    const float* fc1_b  = (const float*)d_in[11];
    const float* fc2_w  = (const float*)d_in[12];
    const float* fc2_b  = (const float*)d_in[13];
    const float* ls2    = (const float*)d_in[14];
    float* out = (float*)d_out;

    float *xn, *qkvb, *attn, *x1, *hb;
    cudaGetSymbolAddress((void**)&xn,   g_xn);
    cudaGetSymbolAddress((void**)&qkvb, g_qkv);
    cudaGetSymbolAddress((void**)&attn, g_attn);
    cudaGetSymbolAddress((void**)&x1,   g_x1);
    cudaGetSymbolAddress((void**)&hb,   g_h);

    // 1. LN1
    ln_kernel<<<TOTAL, 256>>>(x, n1w, n1b, xn);
    // 2. QKV GEMM: (4608,768) x (2304,768)^T
    sgemm_tn<0><<<dim3(36, 18), 256>>>(xn, qkv_w, qkv_b, qkvb, 768, 2304, nullptr, nullptr);
    // 3. ragged flash attention
    attn_kernel<<<dim3(72, 12), 256>>>(qkvb, attn);
    // 4. proj GEMM + residual + layerscale -> x1
    sgemm_tn<2><<<dim3(36, 6), 256>>>(attn, proj_w, proj_b, x1, 768, 768, x, ls1);
    // 5. LN2
    ln_kernel<<<TOTAL, 256>>>(x1, n2w, n2b, xn);
    // 6. fc1 GEMM + exact GELU
    sgemm_tn<1><<<dim3(36, 24), 256>>>(xn, fc1_w, fc1_b, hb, 768, 3072, nullptr, nullptr);
    // 7. fc2 GEMM + residual + layerscale -> out
    sgemm_tn<2><<<dim3(36, 6), 256>>>(hb, fc2_w, fc2_b, out, 3072, 768, x1, ls2);
}

// round 3
// speedup vs baseline: 1.9787x; 1.9787x over previous
#include <cuda_runtime.h>
#include <math.h>
#include <cstdint>

#define TOTAL 4608
#define DMODEL 768
#define DFF 3072

// -------- scratch --------
__device__ float g_xn  [TOTAL * DMODEL];
__device__ float g_qkv [TOTAL * 3 * DMODEL];
__device__ float g_attn[TOTAL * DMODEL];
__device__ float g_x1  [TOTAL * DMODEL];
__device__ float g_h   [TOTAL * DFF];

__constant__ int c_cu[9]  = {0, 1024, 1920, 2688, 3328, 3840, 4288, 4544, 4608};
__constant__ int c_pfx[9] = {0, 16, 30, 42, 52, 60, 67, 71, 72};

// ---------------- LayerNorm ----------------
__global__ __launch_bounds__(256) void ln_kernel(const float* __restrict__ x,
                                                 const float* __restrict__ w,
                                                 const float* __restrict__ b,
                                                 float* __restrict__ out) {
    int row = blockIdx.x;
    const float* xr = x + (size_t)row * DMODEL;
    int t = threadIdx.x;
    float v[3];
    float s = 0.f, ss = 0.f;
#pragma unroll
    for (int i = 0; i < 3; i++) {
        v[i] = xr[t + 256 * i];
        s += v[i];
        ss += v[i] * v[i];
    }
#pragma unroll
    for (int off = 16; off; off >>= 1) {
        s  += __shfl_xor_sync(0xffffffffu, s, off);
        ss += __shfl_xor_sync(0xffffffffu, ss, off);
    }
    __shared__ float sh[16];
    if ((t & 31) == 0) { sh[t >> 5] = s; sh[(t >> 5) + 8] = ss; }
    __syncthreads();
    float ts = 0.f, tss = 0.f;
#pragma unroll
    for (int i = 0; i < 8; i++) { ts += sh[i]; tss += sh[i + 8]; }
    float mu  = ts * (1.f / DMODEL);
    float var = tss * (1.f / DMODEL) - mu * mu;
    float rstd = rsqrtf(var + 1e-6f);
    float* orow = out + (size_t)row * DMODEL;
#pragma unroll
    for (int i = 0; i < 3; i++) {
        int c = t + 256 * i;
        orow[c] = (v[i] - mu) * rstd * w[c] + b[c];
    }
}

// ---------------- TF32 mma.sync GEMM: C[M,N] = A[M,K] @ B[N,K]^T ----------------
// 128x128 CTA tile, BK=32, 8 warps (2m x 4n), warp tile 64x32, m16n8k8 atoms.
// EPI 0: +bias   EPI 1: +bias,GELU   EPI 2: res + gamma*(acc+bias)

__device__ __forceinline__ uint32_t f2tf32(float x) {
    uint32_t u;
    asm("cvt.rna.tf32.f32 %0, %1;" : "=r"(u) : "f"(x));
    return u;
}

#define SKP 36  // smem row stride (uints): 128-float row + pad -> conflict-free frags

template <int EPI>
__global__ __launch_bounds__(256, 1)
void gemm_mma(const float* __restrict__ A, const float* __restrict__ B,
              const float* __restrict__ bias, float* __restrict__ C,
              int K, int N, const float* __restrict__ res, const float* __restrict__ gamma) {
    __shared__ uint32_t As[128 * SKP];
    __shared__ uint32_t Bs[128 * SKP];

    int tid = threadIdx.x, wid = tid >> 5, lane = tid & 31;
    int g = lane >> 2, t4 = lane & 3;
    int mw = (wid & 1) * 64;        // warp m offset in tile
    int nw = (wid >> 1) * 32;       // warp n offset in tile
    int bm = blockIdx.x * 128, bn = blockIdx.y * 128;

    float acc[4][4][4];
#pragma unroll
    for (int i = 0; i < 4; i++)
#pragma unroll
        for (int j = 0; j < 4; j++)
#pragma unroll
            for (int q = 0; q < 4; q++) acc[i][j][q] = 0.f;

    // staging map: fi = tid + 256*j -> row = fi>>3 (0..127), col4 = fi&7 (float4 col)
    const float* Ag[4];
    const float* Bg[4];
#pragma unroll
    for (int j = 0; j < 4; j++) {
        int fi = tid + 256 * j;
        int row = fi >> 3, c4 = fi & 7;
        Ag[j] = A + (size_t)(bm + row) * K + c4 * 4;
        Bg[j] = B + (size_t)(bn + row) * K + c4 * 4;
    }

    float4 av[4], bv[4];
#pragma unroll
    for (int j = 0; j < 4; j++) { av[j] = *(const float4*)Ag[j]; bv[j] = *(const float4*)Bg[j]; }

    int NC = K >> 5;
    for (int c = 0; c < NC; c++) {
        __syncthreads();
#pragma unroll
        for (int j = 0; j < 4; j++) {
            int fi = tid + 256 * j;
            int row = fi >> 3, c4 = fi & 7;
            uint32_t* ap = &As[row * SKP + c4 * 4];
            uint32_t* bp = &Bs[row * SKP + c4 * 4];
            *(uint4*)ap = make_uint4(f2tf32(av[j].x), f2tf32(av[j].y), f2tf32(av[j].z), f2tf32(av[j].w));
            *(uint4*)bp = make_uint4(f2tf32(bv[j].x), f2tf32(bv[j].y), f2tf32(bv[j].z), f2tf32(bv[j].w));
        }
        __syncthreads();
        if (c + 1 < NC) {
#pragma unroll
            for (int j = 0; j < 4; j++) {
                Ag[j] += 32; Bg[j] += 32;
                av[j] = *(const float4*)Ag[j];
                bv[j] = *(const float4*)Bg[j];
            }
        }
#pragma unroll
        for (int s = 0; s < 4; s++) {
            uint32_t af[4][4], bf[4][2];
#pragma unroll
            for (int mt = 0; mt < 4; mt++) {
                int r0 = (mw + mt * 16 + g) * SKP;
                int kk = t4 + 8 * s;
                af[mt][0] = As[r0 + kk];
                af[mt][1] = As[r0 + 8 * SKP + kk];
                af[mt][2] = As[r0 + kk + 4];
                af[mt][3] = As[r0 + 8 * SKP + kk + 4];
            }
#pragma unroll
            for (int nt = 0; nt < 4; nt++) {
                int r0 = (nw + nt * 8 + g) * SKP;
                int kk = t4 + 8 * s;
                bf[nt][0] = Bs[r0 + kk];
                bf[nt][1] = Bs[r0 + kk + 4];
            }
#pragma unroll
            for (int mt = 0; mt < 4; mt++)
#pragma unroll
                for (int nt = 0; nt < 4; nt++) {
                    asm volatile(
                        "mma.sync.aligned.m16n8k8.row.col.f32.tf32.tf32.f32 "
                        "{%0,%1,%2,%3}, {%4,%5,%6,%7}, {%8,%9}, {%0,%1,%2,%3};"
                        : "+f"(acc[mt][nt][0]), "+f"(acc[mt][nt][1]),
                          "+f"(acc[mt][nt][2]), "+f"(acc[mt][nt][3])
                        : "r"(af[mt][0]), "r"(af[mt][1]), "r"(af[mt][2]), "r"(af[mt][3]),
                          "r"(bf[nt][0]), "r"(bf[nt][1]));
                }
        }
    }

    // ---- epilogue ----
#pragma unroll
    for (int mt = 0; mt < 4; mt++) {
#pragma unroll
        for (int half = 0; half < 2; half++) {
            int r = bm + mw + mt * 16 + g + half * 8;
            float* Crow = C + (size_t)r * N;
            const float* resr = (EPI == 2) ? res + (size_t)r * N : nullptr;
#pragma unroll
            for (int nt = 0; nt < 4; nt++) {
                int cn = bn + nw + nt * 8 + 2 * t4;
                float v0 = acc[mt][nt][half * 2 + 0] + bias[cn];
                float v1 = acc[mt][nt][half * 2 + 1] + bias[cn + 1];
                if (EPI == 1) {
                    v0 = 0.5f * v0 * (1.f + erff(v0 * 0.70710678118654752f));
                    v1 = 0.5f * v1 * (1.f + erff(v1 * 0.70710678118654752f));
                }
                if (EPI == 2) {
                    v0 = resr[cn] + gamma[cn] * v0;
                    v1 = resr[cn + 1] + gamma[cn + 1] * v1;
                }
                *(float2*)(Crow + cn) = make_float2(v0, v1);
            }
        }
    }
}

// ---------------- Flash attention (unchanged) ----------------
__global__ __launch_bounds__(256) void attn_kernel(const float* __restrict__ qkv,
                                                   float* __restrict__ out) {
    __shared__ float Qt[64][64];
    __shared__ float Kt[64][64];
    __shared__ float Vs[64][64];
    __shared__ float Pk[64][65];

    int bx = blockIdx.x;
    int h  = blockIdx.y;
    int s = 0;
#pragma unroll
    for (int i = 1; i < 8; i++) s += (bx >= c_pfx[i]) ? 1 : 0;
    int q0   = (bx - c_pfx[s]) * 64;
    int base = c_cu[s];
    int L    = c_cu[s + 1] - base;

    int tid = threadIdx.x;
    int tq = tid >> 4, tk = tid & 15;
    int ltok = tid >> 2;
    int dg   = (tid & 3) << 4;

    {
        int r = q0 + ltok;
        if (r < L) {
            const float* p = qkv + (size_t)(base + r) * 2304 + h * 64 + dg;
            float4 r0 = *(const float4*)(p);
            float4 r1 = *(const float4*)(p + 4);
            float4 r2 = *(const float4*)(p + 8);
            float4 r3 = *(const float4*)(p + 12);
            Qt[dg +  0][ltok] = r0.x; Qt[dg +  1][ltok] = r0.y; Qt[dg +  2][ltok] = r0.z; Qt[dg +  3][ltok] = r0.w;
            Qt[dg +  4][ltok] = r1.x; Qt[dg +  5][ltok] = r1.y; Qt[dg +  6][ltok] = r1.z; Qt[dg +  7][ltok] = r1.w;
            Qt[dg +  8][ltok] = r2.x; Qt[dg +  9][ltok] = r2.y; Qt[dg + 10][ltok] = r2.z; Qt[dg + 11][ltok] = r2.w;
            Qt[dg + 12][ltok] = r3.x; Qt[dg + 13][ltok] = r3.y; Qt[dg + 14][ltok] = r3.z; Qt[dg + 15][ltok] = r3.w;
        } else {
#pragma unroll
            for (int c = 0; c < 16; c++) Qt[dg + c][ltok] = 0.f;
        }
    }

    float m[4], l[4], acc[4][4];
#pragma unroll
    for (int i = 0; i < 4; i++) {
        m[i] = -1e30f; l[i] = 0.f;
#pragma unroll
        for (int j = 0; j < 4; j++) acc[i][j] = 0.f;
    }

    int nkt = (L + 63) >> 6;
    for (int kt = 0; kt < nkt; kt++) {
        int kb = kt << 6;
        __syncthreads();
        {
            int r = kb + ltok;
            if (r < L) {
                const float* kp = qkv + (size_t)(base + r) * 2304 + 768 + h * 64 + dg;
                float4 k0 = *(const float4*)(kp);
                float4 k1 = *(const float4*)(kp + 4);
                float4 k2 = *(const float4*)(kp + 8);
                float4 k3 = *(const float4*)(kp + 12);
                Kt[dg +  0][ltok] = k0.x; Kt[dg +  1][ltok] = k0.y; Kt[dg +  2][ltok] = k0.z; Kt[dg +  3][ltok] = k0.w;
                Kt[dg +  4][ltok] = k1.x; Kt[dg +  5][ltok] = k1.y; Kt[dg +  6][ltok] = k1.z; Kt[dg +  7][ltok] = k1.w;
                Kt[dg +  8][ltok] = k2.x; Kt[dg +  9][ltok] = k2.y; Kt[dg + 10][ltok] = k2.z; Kt[dg + 11][ltok] = k2.w;
                Kt[dg + 12][ltok] = k3.x; Kt[dg + 13][ltok] = k3.y; Kt[dg + 14][ltok] = k3.z; Kt[dg + 15][ltok] = k3.w;
                const float* vp = kp + 768;
                float4 v0 = *(const float4*)(vp);
                float4 v1 = *(const float4*)(vp + 4);
                float4 v2 = *(const float4*)(vp + 8);
                float4 v3 = *(const float4*)(vp + 12);
                ((float4*)Vs[ltok])[(dg >> 2) + 0] = v0;
                ((float4*)Vs[ltok])[(dg >> 2) + 1] = v1;
                ((float4*)Vs[ltok])[(dg >> 2) + 2] = v2;
                ((float4*)Vs[ltok])[(dg >> 2) + 3] = v3;
            } else {
#pragma unroll
                for (int c = 0; c < 16; c++) { Kt[dg + c][ltok] = 0.f; Vs[ltok][dg + c] = 0.f; }
            }
        }
        __syncthreads();

        float sreg[4][4] = {};
#pragma unroll 8
        for (int d = 0; d < 64; d++) {
            float4 qv = ((const float4*)Qt[d])[tq];
            float4 kv = ((const float4*)Kt[d])[tk];
            sreg[0][0] += qv.x * kv.x; sreg[0][1] += qv.x * kv.y; sreg[0][2] += qv.x * kv.z; sreg[0][3] += qv.x * kv.w;
            sreg[1][0] += qv.y * kv.x; sreg[1][1] += qv.y * kv.y; sreg[1][2] += qv.y * kv.z; sreg[1][3] += qv.y * kv.w;
            sreg[2][0] += qv.z * kv.x; sreg[2][1] += qv.z * kv.y; sreg[2][2] += qv.z * kv.z; sreg[2][3] += qv.z * kv.w;
            sreg[3][0] += qv.w * kv.x; sreg[3][1] += qv.w * kv.y; sreg[3][2] += qv.w * kv.z; sreg[3][3] += qv.w * kv.w;
        }

        float alpha[4];
#pragma unroll
        for (int i = 0; i < 4; i++) {
            float rmax = -1e30f;
#pragma unroll
            for (int j = 0; j < 4; j++) {
                float sv = sreg[i][j] * 0.125f;
                if (kb + 4 * tk + j >= L) sv = -1e30f;
                sreg[i][j] = sv;
                rmax = fmaxf(rmax, sv);
            }
#pragma unroll
            for (int off = 8; off; off >>= 1)
                rmax = fmaxf(rmax, __shfl_xor_sync(0xffffffffu, rmax, off));
            float nm = fmaxf(m[i], rmax);
            alpha[i] = __expf(m[i] - nm);
            m[i] = nm;
            float rs = 0.f;
#pragma unroll
            for (int j = 0; j < 4; j++) {
                float p = __expf(sreg[i][j] - nm);
                sreg[i][j] = p;
                rs += p;
            }
#pragma unroll
            for (int off = 8; off; off >>= 1)
                rs += __shfl_xor_sync(0xffffffffu, rs, off);
            l[i] = l[i] * alpha[i] + rs;
        }
#pragma unroll
        for (int i = 0; i < 4; i++)
#pragma unroll
            for (int j = 0; j < 4; j++) {
                Pk[4 * tk + j][4 * tq + i] = sreg[i][j];
                acc[i][j] *= alpha[i];
            }
        __syncthreads();

#pragma unroll 4
        for (int k = 0; k < 64; k++) {
            float4 vv = ((const float4*)Vs[k])[tk];
            float p0 = Pk[k][4 * tq + 0];
            float p1 = Pk[k][4 * tq + 1];
            float p2 = Pk[k][4 * tq + 2];
            float p3 = Pk[k][4 * tq + 3];
            acc[0][0] += p0 * vv.x; acc[0][1] += p0 * vv.y; acc[0][2] += p0 * vv.z; acc[0][3] += p0 * vv.w;
            acc[1][0] += p1 * vv.x; acc[1][1] += p1 * vv.y; acc[1][2] += p1 * vv.z; acc[1][3] += p1 * vv.w;
            acc[2][0] += p2 * vv.x; acc[2][1] += p2 * vv.y; acc[2][2] += p2 * vv.z; acc[2][3] += p2 * vv.w;
            acc[3][0] += p3 * vv.x; acc[3][1] += p3 * vv.y; acc[3][2] += p3 * vv.z; acc[3][3] += p3 * vv.w;
        }
    }

#pragma unroll
    for (int i = 0; i < 4; i++) {
        int r = q0 + 4 * tq + i;
        if (r < L) {
            float inv = 1.f / l[i];
            float4 o;
            o.x = acc[i][0] * inv; o.y = acc[i][1] * inv;
            o.z = acc[i][2] * inv; o.w = acc[i][3] * inv;
            *(float4*)(out + (size_t)(base + r) * 768 + h * 64 + 4 * tk) = o;
        }
    }
}

// ---------------- launch ----------------
extern "C" void kernel_launch(void* const* d_in, const int* in_sizes, int n_in,
                              void* d_out, int out_size) {
    const float* x      = (const float*)d_in[0];
    const float* n1w    = (const float*)d_in[1];
    const float* n1b    = (const float*)d_in[2];
    const float* qkv_w  = (const float*)d_in[3];
    const float* qkv_b  = (const float*)d_in[4];
    const float* proj_w = (const float*)d_in[5];
    const float* proj_b = (const float*)d_in[6];
    const float* ls1    = (const float*)d_in[7];
    const float* n2w    = (const float*)d_in[8];
    const float* n2b    = (const float*)d_in[9];
    const float* fc1_w  = (const float*)d_in[10];
    const float* fc1_b  = (const float*)d_in[11];
    const float* fc2_w  = (const float*)d_in[12];
    const float* fc2_b  = (const float*)d_in[13];
    const float* ls2    = (const float*)d_in[14];
    float* out = (float*)d_out;

    float *xn, *qkvb, *attn, *x1, *hb;
    cudaGetSymbolAddress((void**)&xn,   g_xn);
    cudaGetSymbolAddress((void**)&qkvb, g_qkv);
    cudaGetSymbolAddress((void**)&attn, g_attn);
    cudaGetSymbolAddress((void**)&x1,   g_x1);
    cudaGetSymbolAddress((void**)&hb,   g_h);

    ln_kernel<<<TOTAL, 256>>>(x, n1w, n1b, xn);
    gemm_mma<0><<<dim3(36, 18), 256>>>(xn, qkv_w, qkv_b, qkvb, 768, 2304, nullptr, nullptr);
    attn_kernel<<<dim3(72, 12), 256>>>(qkvb, attn);
    gemm_mma<2><<<dim3(36, 6), 256>>>(attn, proj_w, proj_b, x1, 768, 768, x, ls1);
    ln_kernel<<<TOTAL, 256>>>(x1, n2w, n2b, xn);
    gemm_mma<1><<<dim3(36, 24), 256>>>(xn, fc1_w, fc1_b, hb, 768, 3072, nullptr, nullptr);
    gemm_mma<2><<<dim3(36, 6), 256>>>(hb, fc2_w, fc2_b, out, 3072, 768, x1, ls2);
}

// round 5
// speedup vs baseline: 2.6375x; 1.3329x over previous
#include <cuda_runtime.h>
#include <math.h>
#include <cstdint>

#define TOTAL 4608
#define DMODEL 768
#define DFF 3072

// -------- scratch --------
__device__ float g_xn  [TOTAL * DMODEL];
__device__ float g_qkv [TOTAL * 3 * DMODEL];
__device__ float g_attn[TOTAL * DMODEL];
__device__ float g_x1  [TOTAL * DMODEL];
__device__ float g_h   [TOTAL * DFF];

__constant__ int c_cu[9]    = {0, 1024, 1920, 2688, 3328, 3840, 4288, 4544, 4608};
__constant__ int c_pfx128[9] = {0, 8, 15, 21, 26, 30, 34, 36, 37}; // prefix of ceil(L/128)

__device__ __forceinline__ uint32_t f2tf32(float x) {
    uint32_t u;
    asm("cvt.rna.tf32.f32 %0, %1;" : "=r"(u) : "f"(x));
    return u;
}

// fast exp on FMA pipe (no MUFU): exp(x) = 2^(x*log2e), poly deg-5, branchless
__device__ __forceinline__ float fexp(float x) {
    float t = x * 1.4426950408889634f;
    t = fmaxf(t, -126.0f);
    float n = rintf(t);
    float f = t - n;
    float p = 1.3333558146e-3f;
    p = fmaf(p, f, 9.6181291e-3f);
    p = fmaf(p, f, 5.5504109e-2f);
    p = fmaf(p, f, 2.4022651e-1f);
    p = fmaf(p, f, 6.9314718e-1f);
    p = fmaf(p, f, 1.0f);
    return __int_as_float(__float_as_int(p) + (((int)n) << 23));
}

// ---------------- LayerNorm ----------------
__global__ __launch_bounds__(256) void ln_kernel(const float* __restrict__ x,
                                                 const float* __restrict__ w,
                                                 const float* __restrict__ b,
                                                 float* __restrict__ out) {
    int row = blockIdx.x;
    const float* xr = x + (size_t)row * DMODEL;
    int t = threadIdx.x;
    float v[3];
    float s = 0.f, ss = 0.f;
#pragma unroll
    for (int i = 0; i < 3; i++) {
        v[i] = xr[t + 256 * i];
        s += v[i];
        ss += v[i] * v[i];
    }
#pragma unroll
    for (int off = 16; off; off >>= 1) {
        s  += __shfl_xor_sync(0xffffffffu, s, off);
        ss += __shfl_xor_sync(0xffffffffu, ss, off);
    }
    __shared__ float sh[16];
    if ((t & 31) == 0) { sh[t >> 5] = s; sh[(t >> 5) + 8] = ss; }
    __syncthreads();
    float ts = 0.f, tss = 0.f;
#pragma unroll
    for (int i = 0; i < 8; i++) { ts += sh[i]; tss += sh[i + 8]; }
    float mu  = ts * (1.f / DMODEL);
    float var = tss * (1.f / DMODEL) - mu * mu;
    float rstd = rsqrtf(var + 1e-6f);
    float* orow = out + (size_t)row * DMODEL;
#pragma unroll
    for (int i = 0; i < 3; i++) {
        int c = t + 256 * i;
        orow[c] = (v[i] - mu) * rstd * w[c] + b[c];
    }
}

// ---------------- TF32 mma.sync GEMM ----------------
#define SKP 36

template <int EPI>
__global__ __launch_bounds__(256, 1)
void gemm_mma(const float* __restrict__ A, const float* __restrict__ B,
              const float* __restrict__ bias, float* __restrict__ C,
              int K, int N, const float* __restrict__ res, const float* __restrict__ gamma) {
    __shared__ uint32_t As[128 * SKP];
    __shared__ uint32_t Bs[128 * SKP];

    int tid = threadIdx.x, wid = tid >> 5, lane = tid & 31;
    int g = lane >> 2, t4 = lane & 3;
    int mw = (wid & 1) * 64;
    int nw = (wid >> 1) * 32;
    int bm = blockIdx.x * 128, bn = blockIdx.y * 128;

    float acc[4][4][4];
#pragma unroll
    for (int i = 0; i < 4; i++)
#pragma unroll
        for (int j = 0; j < 4; j++)
#pragma unroll
            for (int q = 0; q < 4; q++) acc[i][j][q] = 0.f;

    const float* Ag[4];
    const float* Bg[4];
#pragma unroll
    for (int j = 0; j < 4; j++) {
        int fi = tid + 256 * j;
        int row = fi >> 3, c4 = fi & 7;
        Ag[j] = A + (size_t)(bm + row) * K + c4 * 4;
        Bg[j] = B + (size_t)(bn + row) * K + c4 * 4;
    }

    float4 av[4], bv[4];
#pragma unroll
    for (int j = 0; j < 4; j++) { av[j] = *(const float4*)Ag[j]; bv[j] = *(const float4*)Bg[j]; }

    int NC = K >> 5;
    for (int c = 0; c < NC; c++) {
        __syncthreads();
#pragma unroll
        for (int j = 0; j < 4; j++) {
            int fi = tid + 256 * j;
            int row = fi >> 3, c4 = fi & 7;
            uint32_t* ap = &As[row * SKP + c4 * 4];
            uint32_t* bp = &Bs[row * SKP + c4 * 4];
            *(uint4*)ap = make_uint4(f2tf32(av[j].x), f2tf32(av[j].y), f2tf32(av[j].z), f2tf32(av[j].w));
            *(uint4*)bp = make_uint4(f2tf32(bv[j].x), f2tf32(bv[j].y), f2tf32(bv[j].z), f2tf32(bv[j].w));
        }
        __syncthreads();
        if (c + 1 < NC) {
#pragma unroll
            for (int j = 0; j < 4; j++) {
                Ag[j] += 32; Bg[j] += 32;
                av[j] = *(const float4*)Ag[j];
                bv[j] = *(const float4*)Bg[j];
            }
        }
#pragma unroll
        for (int s = 0; s < 4; s++) {
            uint32_t af[4][4], bf[4][2];
#pragma unroll
            for (int mt = 0; mt < 4; mt++) {
                int r0 = (mw + mt * 16 + g) * SKP;
                int kk = t4 + 8 * s;
                af[mt][0] = As[r0 + kk];
                af[mt][1] = As[r0 + 8 * SKP + kk];
                af[mt][2] = As[r0 + kk + 4];
                af[mt][3] = As[r0 + 8 * SKP + kk + 4];
            }
#pragma unroll
            for (int nt = 0; nt < 4; nt++) {
                int r0 = (nw + nt * 8 + g) * SKP;
                int kk = t4 + 8 * s;
                bf[nt][0] = Bs[r0 + kk];
                bf[nt][1] = Bs[r0 + kk + 4];
            }
#pragma unroll
            for (int mt = 0; mt < 4; mt++)
#pragma unroll
                for (int nt = 0; nt < 4; nt++) {
                    asm volatile(
                        "mma.sync.aligned.m16n8k8.row.col.f32.tf32.tf32.f32 "
                        "{%0,%1,%2,%3}, {%4,%5,%6,%7}, {%8,%9}, {%0,%1,%2,%3};"
                        : "+f"(acc[mt][nt][0]), "+f"(acc[mt][nt][1]),
                          "+f"(acc[mt][nt][2]), "+f"(acc[mt][nt][3])
                        : "r"(af[mt][0]), "r"(af[mt][1]), "r"(af[mt][2]), "r"(af[mt][3]),
                          "r"(bf[nt][0]), "r"(bf[nt][1]));
                }
        }
    }

#pragma unroll
    for (int mt = 0; mt < 4; mt++) {
#pragma unroll
        for (int half = 0; half < 2; half++) {
            int r = bm + mw + mt * 16 + g + half * 8;
            float* Crow = C + (size_t)r * N;
            const float* resr = (EPI == 2) ? res + (size_t)r * N : nullptr;
#pragma unroll
            for (int nt = 0; nt < 4; nt++) {
                int cn = bn + nw + nt * 8 + 2 * t4;
                float v0 = acc[mt][nt][half * 2 + 0] + bias[cn];
                float v1 = acc[mt][nt][half * 2 + 1] + bias[cn + 1];
                if (EPI == 1) {
                    v0 = 0.5f * v0 * (1.f + erff(v0 * 0.70710678118654752f));
                    v1 = 0.5f * v1 * (1.f + erff(v1 * 0.70710678118654752f));
                }
                if (EPI == 2) {
                    v0 = resr[cn] + gamma[cn] * v0;
                    v1 = resr[cn + 1] + gamma[cn + 1] * v1;
                }
                *(float2*)(Crow + cn) = make_float2(v0, v1);
            }
        }
    }
}

// ---------------- Flash attention with TF32 mma ----------------
// block: 256 thr / 8 warps; q-tile 128 rows, k-tile 64 keys, head dim 64.
// smem layout (uints, stride 68): Qs[128], Ks[64], Vt[64] (transposed), Ps[128]
#define AST 68
#define A_QS 0
#define A_KS (128 * AST)
#define A_VT (A_KS + 64 * AST)
#define A_PS (A_VT + 64 * AST)
#define A_SMEM_BYTES ((A_PS + 128 * AST) * 4)

__global__ __launch_bounds__(256) void attn_mma_kernel(const float* __restrict__ qkv,
                                                       float* __restrict__ out) {
    extern __shared__ uint32_t sm[];

    int bx = blockIdx.x, h = blockIdx.y;
    int s = 0;
#pragma unroll
    for (int i = 1; i < 8; i++) s += (bx >= c_pfx128[i]) ? 1 : 0;
    int q0   = (bx - c_pfx128[s]) * 128;
    int base = c_cu[s];
    int L    = c_cu[s + 1] - base;

    int tid = threadIdx.x, wid = tid >> 5, lane = tid & 31;
    int g = lane >> 2, t4 = lane & 3;
    int mw = wid * 16;
    int ltok = tid >> 2;
    int dg   = (tid & 3) * 16;

    // ---- load Q tile (scaled by 1/8, tf32) ----
#pragma unroll
    for (int half = 0; half < 2; half++) {
        int row = ltok + half * 64;
        int r = q0 + row;
        uint32_t* qrow = &sm[A_QS + row * AST + dg];
        if (r < L) {
            const float* p = qkv + (size_t)(base + r) * 2304 + h * 64 + dg;
#pragma unroll
            for (int j = 0; j < 4; j++) {
                float4 v = *(const float4*)(p + j * 4);
                *(uint4*)(qrow + j * 4) = make_uint4(
                    f2tf32(v.x * 0.125f), f2tf32(v.y * 0.125f),
                    f2tf32(v.z * 0.125f), f2tf32(v.w * 0.125f));
            }
        } else {
#pragma unroll
            for (int j = 0; j < 4; j++) *(uint4*)(qrow + j * 4) = make_uint4(0, 0, 0, 0);
        }
    }

    float m0 = -1e30f, m1 = -1e30f, l0 = 0.f, l1 = 0.f;
    float acco[8][4];
#pragma unroll
    for (int nt = 0; nt < 8; nt++)
#pragma unroll
        for (int q = 0; q < 4; q++) acco[nt][q] = 0.f;

    int nkt = (L + 63) >> 6;
    for (int kt = 0; kt < nkt; kt++) {
        int kb = kt << 6;
        __syncthreads();
        // ---- load K (row-major) and V (transposed) tiles ----
        {
            int r = kb + ltok;
            uint32_t* krow = &sm[A_KS + ltok * AST + dg];
            if (r < L) {
                const float* kp = qkv + (size_t)(base + r) * 2304 + 768 + h * 64 + dg;
#pragma unroll
                for (int j = 0; j < 4; j++) {
                    float4 v = *(const float4*)(kp + j * 4);
                    *(uint4*)(krow + j * 4) = make_uint4(f2tf32(v.x), f2tf32(v.y), f2tf32(v.z), f2tf32(v.w));
                }
                const float* vp = kp + 768;
#pragma unroll
                for (int j = 0; j < 4; j++) {
                    float4 v = *(const float4*)(vp + j * 4);
                    sm[A_VT + (dg + j * 4 + 0) * AST + ltok] = f2tf32(v.x);
                    sm[A_VT + (dg + j * 4 + 1) * AST + ltok] = f2tf32(v.y);
                    sm[A_VT + (dg + j * 4 + 2) * AST + ltok] = f2tf32(v.z);
                    sm[A_VT + (dg + j * 4 + 3) * AST + ltok] = f2tf32(v.w);
                }
            } else {
#pragma unroll
                for (int j = 0; j < 4; j++) *(uint4*)(krow + j * 4) = make_uint4(0, 0, 0, 0);
#pragma unroll
                for (int c = 0; c < 16; c++) sm[A_VT + (dg + c) * AST + ltok] = 0;
            }
        }
        __syncthreads();

        // ---- S = Q K^T ----
        float sc[8][4];
#pragma unroll
        for (int nt = 0; nt < 8; nt++)
#pragma unroll
            for (int q = 0; q < 4; q++) sc[nt][q] = 0.f;
#pragma unroll
        for (int s8 = 0; s8 < 8; s8++) {
            int kk = t4 + 8 * s8;
            uint32_t a0 = sm[A_QS + (mw + g) * AST + kk];
            uint32_t a1 = sm[A_QS + (mw + 8 + g) * AST + kk];
            uint32_t a2 = sm[A_QS + (mw + g) * AST + kk + 4];
            uint32_t a3 = sm[A_QS + (mw + 8 + g) * AST + kk + 4];
#pragma unroll
            for (int nt = 0; nt < 8; nt++) {
                uint32_t b0 = sm[A_KS + (nt * 8 + g) * AST + kk];
                uint32_t b1 = sm[A_KS + (nt * 8 + g) * AST + kk + 4];
                asm volatile(
                    "mma.sync.aligned.m16n8k8.row.col.f32.tf32.tf32.f32 "
                    "{%0,%1,%2,%3}, {%4,%5,%6,%7}, {%8,%9}, {%0,%1,%2,%3};"
                    : "+f"(sc[nt][0]), "+f"(sc[nt][1]), "+f"(sc[nt][2]), "+f"(sc[nt][3])
                    : "r"(a0), "r"(a1), "r"(a2), "r"(a3), "r"(b0), "r"(b1));
            }
        }

        // ---- mask + online softmax ----
        bool full = (kb + 64 <= L);
        if (!full) {
#pragma unroll
            for (int nt = 0; nt < 8; nt++)
#pragma unroll
                for (int c = 0; c < 2; c++) {
                    int col = kb + nt * 8 + 2 * t4 + c;
                    if (col >= L) { sc[nt][c] = -1e30f; sc[nt][2 + c] = -1e30f; }
                }
        }
        float rmax0 = -1e30f, rmax1 = -1e30f;
#pragma unroll
        for (int nt = 0; nt < 8; nt++) {
            rmax0 = fmaxf(rmax0, fmaxf(sc[nt][0], sc[nt][1]));
            rmax1 = fmaxf(rmax1, fmaxf(sc[nt][2], sc[nt][3]));
        }
#pragma unroll
        for (int off = 1; off <= 2; off <<= 1) {
            rmax0 = fmaxf(rmax0, __shfl_xor_sync(0xffffffffu, rmax0, off));
            rmax1 = fmaxf(rmax1, __shfl_xor_sync(0xffffffffu, rmax1, off));
        }
        float nm0 = fmaxf(m0, rmax0), nm1 = fmaxf(m1, rmax1);
        float alpha0 = fexp(m0 - nm0), alpha1 = fexp(m1 - nm1);
        m0 = nm0; m1 = nm1;
        float rs0 = 0.f, rs1 = 0.f;
#pragma unroll
        for (int nt = 0; nt < 8; nt++) {
            int colb = nt * 8 + 2 * t4;
#pragma unroll
            for (int c = 0; c < 2; c++) {
                float p0 = fexp(sc[nt][c] - nm0);
                float p1 = fexp(sc[nt][2 + c] - nm1);
                rs0 += p0; rs1 += p1;
                sm[A_PS + (mw + g) * AST + colb + c]     = f2tf32(p0);
                sm[A_PS + (mw + 8 + g) * AST + colb + c] = f2tf32(p1);
            }
        }
#pragma unroll
        for (int off = 1; off <= 2; off <<= 1) {
            rs0 += __shfl_xor_sync(0xffffffffu, rs0, off);
            rs1 += __shfl_xor_sync(0xffffffffu, rs1, off);
        }
        l0 = l0 * alpha0 + rs0;
        l1 = l1 * alpha1 + rs1;
#pragma unroll
        for (int nt = 0; nt < 8; nt++) {
            acco[nt][0] *= alpha0; acco[nt][1] *= alpha0;
            acco[nt][2] *= alpha1; acco[nt][3] *= alpha1;
        }
        __syncthreads();

        // ---- O += P V ----
#pragma unroll
        for (int s8 = 0; s8 < 8; s8++) {
            int kk = t4 + 8 * s8;
            uint32_t a0 = sm[A_PS + (mw + g) * AST + kk];
            uint32_t a1 = sm[A_PS + (mw + 8 + g) * AST + kk];
            uint32_t a2 = sm[A_PS + (mw + g) * AST + kk + 4];
            uint32_t a3 = sm[A_PS + (mw + 8 + g) * AST + kk + 4];
#pragma unroll
            for (int nt = 0; nt < 8; nt++) {
                uint32_t b0 = sm[A_VT + (nt * 8 + g) * AST + kk];
                uint32_t b1 = sm[A_VT + (nt * 8 + g) * AST + kk + 4];
                asm volatile(
                    "mma.sync.aligned.m16n8k8.row.col.f32.tf32.tf32.f32 "
                    "{%0,%1,%2,%3}, {%4,%5,%6,%7}, {%8,%9}, {%0,%1,%2,%3};"
                    : "+f"(acco[nt][0]), "+f"(acco[nt][1]), "+f"(acco[nt][2]), "+f"(acco[nt][3])
                    : "r"(a0), "r"(a1), "r"(a2), "r"(a3), "r"(b0), "r"(b1));
            }
        }
    }

    // ---- write O ----
    float inv0 = 1.f / l0, inv1 = 1.f / l1;
    int r0 = q0 + mw + g, r1 = r0 + 8;
#pragma unroll
    for (int nt = 0; nt < 8; nt++) {
        int col = h * 64 + nt * 8 + 2 * t4;
        if (r0 < L)
            *(float2*)(out + (size_t)(base + r0) * 768 + col) =
                make_float2(acco[nt][0] * inv0, acco[nt][1] * inv0);
        if (r1 < L)
            *(float2*)(out + (size_t)(base + r1) * 768 + col) =
                make_float2(acco[nt][2] * inv1, acco[nt][3] * inv1);
    }
}

// ---------------- launch ----------------
extern "C" void kernel_launch(void* const* d_in, const int* in_sizes, int n_in,
                              void* d_out, int out_size) {
    const float* x      = (const float*)d_in[0];
    const float* n1w    = (const float*)d_in[1];
    const float* n1b    = (const float*)d_in[2];
    const float* qkv_w  = (const float*)d_in[3];
    const float* qkv_b  = (const float*)d_in[4];
    const float* proj_w = (const float*)d_in[5];
    const float* proj_b = (const float*)d_in[6];
    const float* ls1    = (const float*)d_in[7];
    const float* n2w    = (const float*)d_in[8];
    const float* n2b    = (const float*)d_in[9];
    const float* fc1_w  = (const float*)d_in[10];
    const float* fc1_b  = (const float*)d_in[11];
    const float* fc2_w  = (const float*)d_in[12];
    const float* fc2_b  = (const float*)d_in[13];
    const float* ls2    = (const float*)d_in[14];
    float* out = (float*)d_out;

    float *xn, *qkvb, *attn, *x1, *hb;
    cudaGetSymbolAddress((void**)&xn,   g_xn);
    cudaGetSymbolAddress((void**)&qkvb, g_qkv);
    cudaGetSymbolAddress((void**)&attn, g_attn);
    cudaGetSymbolAddress((void**)&x1,   g_x1);
    cudaGetSymbolAddress((void**)&hb,   g_h);

    cudaFuncSetAttribute(attn_mma_kernel, cudaFuncAttributeMaxDynamicSharedMemorySize, A_SMEM_BYTES);

    ln_kernel<<<TOTAL, 256>>>(x, n1w, n1b, xn);
    gemm_mma<0><<<dim3(36, 18), 256>>>(xn, qkv_w, qkv_b, qkvb, 768, 2304, nullptr, nullptr);
    attn_mma_kernel<<<dim3(37, 12), 256, A_SMEM_BYTES>>>(qkvb, attn);
    gemm_mma<2><<<dim3(36, 6), 256>>>(attn, proj_w, proj_b, x1, 768, 768, x, ls1);
    ln_kernel<<<TOTAL, 256>>>(x1, n2w, n2b, xn);
    gemm_mma<1><<<dim3(36, 24), 256>>>(xn, fc1_w, fc1_b, hb, 768, 3072, nullptr, nullptr);
    gemm_mma<2><<<dim3(36, 6), 256>>>(hb, fc2_w, fc2_b, out, 3072, 768, x1, ls2);
}